// round 7
// baseline (speedup 1.0000x reference)
#include <cuda_runtime.h>
#include <cstdint>

typedef unsigned long long u64;

#define BB   256
#define TT   2048
#define HH   256
#define PP   24
#define BC   2              // batch rows per CTA
#define NCTA (BB/BC)        // 128
#define NTHR 512
#define NREGC 20            // W float4-chunks in registers per thread (80 floats)
#define NSMC  12            // W float4-chunks in smem per thread      (48 floats)

// packed f32x2 FMA: d = a*b + d
__device__ __forceinline__ void fma2(u64 &d, u64 a, u64 b) {
    asm("fma.rn.f32x2 %0, %1, %2, %0;" : "+l"(d) : "l"(a), "l"(b));
}
__device__ __forceinline__ float2 unpk(u64 v) {
    float2 r; asm("mov.b64 {%0, %1}, %2;" : "=f"(r.x), "=f"(r.y) : "l"(v)); return r;
}

// SMEM layout:
//  [0, 96K)     sW[c][t] : W chunk c of thread t (ulonglong2), c < NSMC
//  [96K,100K)   h double buffer [2][BC][HH] floats (XOR-swizzled, see hswz2)
//  [100K,116K)  x stage [BC][TT]
#define SW_BYTES   ((size_t)NSMC * NTHR * 16)
#define HB_BYTES   ((size_t)2 * BC * HH * 4)
#define X_BYTES    ((size_t)BC * TT * 4)
#define SMEM_TOTAL (SW_BYTES + HB_BYTES + X_BYTES)

// storage word (within one 512-float h buffer) for (col, batch):
//   k=col>>5, c=(col>>2)&7, j=col&3
//   float4 index = c*8 + (k ^ c ^ (b?4:0)); batch offset HH words.
// Reads (fixed c, lanes k): 8 distinct float4 in one 8-aligned block -> conflict-free.
// Writes (warp): 32 lanes -> 32 distinct banks -> 1 wavefront.
__device__ __forceinline__ int hswz2(int col, int b) {
    int k = col >> 5, c = (col >> 2) & 7, j = col & 3;
    return b * HH + (((c << 3) | (k ^ c ^ (b ? 4 : 0))) << 2) + j;
}

// fast tanh: 1 - 2/(e^{2x}+1). |err| ~1e-6, branch-free, inf-safe.
__device__ __forceinline__ float ftanh(float x) {
    float e = __expf(x + x);
    return 1.0f - __fdividef(2.0f, e + 1.0f);
}

__global__ void __launch_bounds__(NTHR, 1)
rnn_persistent_kernel(const float* __restrict__ x,
                      const float* __restrict__ W_ih,
                      const float* __restrict__ W_hh,
                      const float* __restrict__ b_ih,
                      const float* __restrict__ b_hh,
                      const float* __restrict__ W_out,
                      const float* __restrict__ b_out,
                      float* __restrict__ out)
{
    extern __shared__ char smem[];
    ulonglong2* sW   = (ulonglong2*)smem;
    float*      hbuf = (float*)(smem + SW_BYTES);
    float*      sx   = (float*)(smem + SW_BYTES + HB_BYTES);

    const int t  = threadIdx.x;
    const int g  = t >> 3;      // row group: rows 4g..4g+3
    const int k  = t & 7;       // column strip: cols 32k..32k+31
    const int b0 = blockIdx.x * BC;

    // ---- Prologue: W chunks. Thread (g,k): rows 4g+j, row-local float4 idx k*8+c.
    const ulonglong2* Wv = (const ulonglong2*)W_hh;   // row stride = 64 float4
    ulonglong2 wr[NREGC];
#pragma unroll
    for (int c = 0; c < 8; c++) wr[c]      = Wv[(size_t)(4*g + 0) * 64 + k*8 + c];
#pragma unroll
    for (int c = 0; c < 8; c++) wr[8 + c]  = Wv[(size_t)(4*g + 1) * 64 + k*8 + c];
#pragma unroll
    for (int c = 0; c < 4; c++) wr[16 + c] = Wv[(size_t)(4*g + 2) * 64 + k*8 + c];
#pragma unroll
    for (int c = 0; c < 4; c++) sW[c * NTHR + t]       = Wv[(size_t)(4*g + 2) * 64 + k*8 + 4 + c];
#pragma unroll
    for (int c = 0; c < 8; c++) sW[(4 + c) * NTHR + t] = Wv[(size_t)(4*g + 3) * 64 + k*8 + c];

    // lane-owned output after reduction: row 4g + (k>>1), batch (k&1)
    const int bsel  = k & 1;
    const int myrow = 4*g + (k >> 1);
    const float bias_l = b_ih[myrow] + b_hh[myrow];
    const float wih_l  = W_ih[myrow];
    const int   wpos   = hswz2(myrow, bsel);

    // stage x[b0:b0+BC, :] into smem (coalesced float4)
    {
        const float4* xg = (const float4*)(x + (size_t)b0 * TT);
        float4*       xs = (float4*)sx;
        for (int q = t; q < BC * TT / 4; q += NTHR) xs[q] = xg[q];
    }
    hbuf[t] = 0.0f;      // zero h buffer 0 (512 floats)
    __syncthreads();

    const bool hb4 = (k & 4) != 0;
    const bool hb2 = (k & 2) != 0;
    const bool hb1 = (k & 1) != 0;
    const float* xrow = sx + bsel * TT;

#define RNN_STEP(RB, WB, TSTEP)                                            \
    {                                                                      \
        const ulonglong2* hr = (const ulonglong2*)(hbuf + (RB));           \
        u64 a0=0,a1=0,a2=0,a3=0,a4=0,a5=0,a6=0,a7=0;                       \
        _Pragma("unroll")                                                  \
        for (int c = 0; c < 8; c++) {                                      \
            const int m0 = k ^ c;                                          \
            ulonglong2 h0 = hr[c*8 + m0];                                  \
            ulonglong2 h1 = hr[64 + c*8 + (m0 ^ 4)];                       \
            ulonglong2 w0 = wr[c];                                         \
            ulonglong2 w1 = wr[8 + c];                                     \
            ulonglong2 w2 = (c < 4) ? wr[16 + c] : sW[(c - 4) * NTHR + t]; \
            ulonglong2 w3 = sW[(4 + c) * NTHR + t];                        \
            fma2(a0, h0.x, w0.x); fma2(a0, h0.y, w0.y);                    \
            fma2(a1, h1.x, w0.x); fma2(a1, h1.y, w0.y);                    \
            fma2(a2, h0.x, w1.x); fma2(a2, h0.y, w1.y);                    \
            fma2(a3, h1.x, w1.x); fma2(a3, h1.y, w1.y);                    \
            fma2(a4, h0.x, w2.x); fma2(a4, h0.y, w2.y);                    \
            fma2(a5, h1.x, w2.x); fma2(a5, h1.y, w2.y);                    \
            fma2(a6, h0.x, w3.x); fma2(a6, h0.y, w3.y);                    \
            fma2(a7, h1.x, w3.x); fma2(a7, h1.y, w3.y);                    \
        }                                                                  \
        float2 f;                                                          \
        f = unpk(a0); float s0 = f.x + f.y;                                \
        f = unpk(a1); float s1 = f.x + f.y;                                \
        f = unpk(a2); float s2 = f.x + f.y;                                \
        f = unpk(a3); float s3 = f.x + f.y;                                \
        f = unpk(a4); float s4 = f.x + f.y;                                \
        f = unpk(a5); float s5 = f.x + f.y;                                \
        f = unpk(a6); float s6 = f.x + f.y;                                \
        f = unpk(a7); float s7 = f.x + f.y;                                \
        float t0 = hb4 ? s4 : s0,  u0 = hb4 ? s0 : s4;                     \
        float t1 = hb4 ? s5 : s1,  u1 = hb4 ? s1 : s5;                     \
        float t2 = hb4 ? s6 : s2,  u2 = hb4 ? s2 : s6;                     \
        float t3 = hb4 ? s7 : s3,  u3 = hb4 ? s3 : s7;                     \
        t0 += __shfl_xor_sync(0xffffffffu, u0, 4);                         \
        t1 += __shfl_xor_sync(0xffffffffu, u1, 4);                         \
        t2 += __shfl_xor_sync(0xffffffffu, u2, 4);                         \
        t3 += __shfl_xor_sync(0xffffffffu, u3, 4);                         \
        float p0 = hb2 ? t2 : t0,  q0 = hb2 ? t0 : t2;                     \
        float p1 = hb2 ? t3 : t1,  q1 = hb2 ? t1 : t3;                     \
        p0 += __shfl_xor_sync(0xffffffffu, q0, 2);                         \
        p1 += __shfl_xor_sync(0xffffffffu, q1, 2);                         \
        float vk = hb1 ? p1 : p0,  vs = hb1 ? p0 : p1;                     \
        vk += __shfl_xor_sync(0xffffffffu, vs, 1);                         \
        float pre = vk + fmaf(xrow[TSTEP], wih_l, bias_l);                 \
        hbuf[(WB) + wpos] = ftanh(pre);                                    \
        __syncthreads();                                                   \
    }

    for (int ts = 0; ts < TT; ts += 2) {
        RNN_STEP(0,        BC * HH, ts)       // read buf0, write buf1
        RNN_STEP(BC * HH,  0,       ts + 1)   // read buf1, write buf0
    }
#undef RNN_STEP

    // ---- Epilogue: out[b,p] = h_T[b,:] . W_out[p,:] + b_out[p]  (h in buf0)
    if (t < BC * PP) {
        const int bb = t / PP;
        const int p  = t % PP;
        const float* wo = W_out + (size_t)p * HH;
        float acc = b_out[p];
#pragma unroll 8
        for (int col = 0; col < HH; col++)
            acc = fmaf(hbuf[hswz2(col, bb)], wo[col], acc);
        out[(size_t)(b0 + bb) * PP + p] = acc;
    }
}

extern "C" void kernel_launch(void* const* d_in, const int* in_sizes, int n_in,
                              void* d_out, int out_size)
{
    const float* x     = (const float*)d_in[0];
    const float* W_ih  = (const float*)d_in[1];
    const float* W_hh  = (const float*)d_in[2];
    const float* b_ih  = (const float*)d_in[3];
    const float* b_hh  = (const float*)d_in[4];
    const float* W_out = (const float*)d_in[5];
    const float* b_out = (const float*)d_in[6];
    float* out = (float*)d_out;

    cudaFuncSetAttribute(rnn_persistent_kernel,
                         cudaFuncAttributeMaxDynamicSharedMemorySize, (int)SMEM_TOTAL);
    rnn_persistent_kernel<<<NCTA, NTHR, SMEM_TOTAL>>>(x, W_ih, W_hh, b_ih, b_hh,
                                                      W_out, b_out, out);
}

// round 8
// speedup vs baseline: 1.2518x; 1.2518x over previous
#include <cuda_runtime.h>
#include <cstdint>

typedef unsigned long long u64;

#define BB   256
#define TT   2048
#define HH   256
#define PP   24
#define BC   2              // batch rows per CTA
#define NCTA (BB/BC)        // 128
#define NTHR 256            // 8 warps; each thread: 8 rows x 32 cols
#define NSMC 24             // W float4-chunks in smem per thread (rows 5,6,7)

// packed f32x2 FMA: d = a*b + d
__device__ __forceinline__ void fma2(u64 &d, u64 a, u64 b) {
    asm("fma.rn.f32x2 %0, %1, %2, %0;" : "+l"(d) : "l"(a), "l"(b));
}
__device__ __forceinline__ float2 unpk(u64 v) {
    float2 r; asm("mov.b64 {%0, %1}, %2;" : "=f"(r.x), "=f"(r.y) : "l"(v)); return r;
}

// SMEM layout:
//  [0, 96K)     sW[c][t] : W chunk c of thread t (ulonglong2), c < NSMC
//  [96K,100K)   h double buffer [2][BC][HH] floats (XOR-swizzled, see hword)
//  [100K,116K)  x stage [BC][TT]
#define SW_BYTES   ((size_t)NSMC * NTHR * 16)
#define HB_BYTES   ((size_t)2 * BC * HH * 4)
#define X_BYTES    ((size_t)BC * TT * 4)
#define SMEM_TOTAL (SW_BYTES + HB_BYTES + X_BYTES)

// storage word (within one 512-float h buffer) for (col, batch):
//   c=(col>>2)&7, kk=col>>5, j=col&3 ; float4 idx = c*8 + (kk^c)
// Reads (fixed c, lanes k=0..7): 8 distinct float4 in an 8-aligned block -> 1 wavefront.
// Writes (warp: rows 8g+k, g spans 4, k spans 8): 32 distinct banks -> 1 wavefront.
__device__ __forceinline__ int hword(int col, int b) {
    int c = (col >> 2) & 7, kk = col >> 5, j = col & 3;
    return b * HH + ((((c << 3) | (kk ^ c)) << 2) | j);
}

// fast tanh: 1 - 2/(e^{2x}+1). |err| ~1e-6, branch-free, inf-safe.
__device__ __forceinline__ float ftanh(float x) {
    float e = __expf(x + x);
    return 1.0f - __fdividef(2.0f, e + 1.0f);
}

__global__ void __launch_bounds__(NTHR, 1)
rnn_persistent_kernel(const float* __restrict__ x,
                      const float* __restrict__ W_ih,
                      const float* __restrict__ W_hh,
                      const float* __restrict__ b_ih,
                      const float* __restrict__ b_hh,
                      const float* __restrict__ W_out,
                      const float* __restrict__ b_out,
                      float* __restrict__ out)
{
    extern __shared__ char smem[];
    ulonglong2* sW   = (ulonglong2*)smem;
    float*      hbuf = (float*)(smem + SW_BYTES);
    float*      sx   = (float*)(smem + SW_BYTES + HB_BYTES);

    const int t  = threadIdx.x;
    const int g  = t >> 3;      // row group: rows 8g..8g+7
    const int k  = t & 7;       // column strip: cols 32k..32k+31
    const int b0 = blockIdx.x * BC;

    // ---- Prologue: thread (g,k) owns rows 8g+j (j<8), row-local float4 idx k*8+c.
    // Rows 0..4 -> registers (40 float4 = 160 regs). Rows 5,6,7 -> smem.
    const ulonglong2* Wv = (const ulonglong2*)W_hh;   // row stride = 64 float4
    ulonglong2 wr[40];
#pragma unroll
    for (int j = 0; j < 5; j++)
#pragma unroll
        for (int c = 0; c < 8; c++)
            wr[j*8 + c] = Wv[(size_t)(8*g + j) * 64 + k*8 + c];
#pragma unroll
    for (int j = 0; j < 3; j++)
#pragma unroll
        for (int c = 0; c < 8; c++)
            sW[(j*8 + c) * NTHR + t] = Wv[(size_t)(8*g + 5 + j) * 64 + k*8 + c];

    // lane-owned outputs after reduction: row 8g+k, both batches
    const int myrow  = 8*g + k;
    const float bias = b_ih[myrow] + b_hh[myrow];
    const float wih  = W_ih[myrow];
    const int wpos0  = hword(myrow, 0);
    const int wpos1  = hword(myrow, 1);

    // stage x[b0:b0+BC, :] into smem (coalesced float4)
    {
        const float4* xg = (const float4*)(x + (size_t)b0 * TT);
        float4*       xs = (float4*)sx;
#pragma unroll
        for (int q = t; q < BC * TT / 4; q += NTHR) xs[q] = xg[q];
    }
    hbuf[t] = 0.0f; hbuf[NTHR + t] = 0.0f;   // zero h buffer 0
    __syncthreads();

    const bool s4 = (k & 4) != 0;
    const bool s2 = (k & 2) != 0;
    const bool s1 = (k & 1) != 0;

    int rb = 0;
    for (int ts = 0; ts < TT; ts++) {
        const ulonglong2* hr = (const ulonglong2*)(hbuf + rb * (BC * HH));

        u64 A[16];   // A[j*2+b]
#pragma unroll
        for (int m = 0; m < 16; m++) A[m] = 0ull;

#pragma unroll
        for (int c = 0; c < 8; c++) {
            const int m0 = k ^ c;
            ulonglong2 h0 = hr[c*8 + m0];
            ulonglong2 h1 = hr[64 + c*8 + m0];
            ulonglong2 w5 = sW[c * NTHR + t];
            ulonglong2 w6 = sW[(8 + c) * NTHR + t];
            ulonglong2 w7 = sW[(16 + c) * NTHR + t];
#pragma unroll
            for (int j = 0; j < 5; j++) {
                ulonglong2 w = wr[j*8 + c];
                fma2(A[j*2],   h0.x, w.x); fma2(A[j*2],   h0.y, w.y);
                fma2(A[j*2+1], h1.x, w.x); fma2(A[j*2+1], h1.y, w.y);
            }
            fma2(A[10], h0.x, w5.x); fma2(A[10], h0.y, w5.y);
            fma2(A[11], h1.x, w5.x); fma2(A[11], h1.y, w5.y);
            fma2(A[12], h0.x, w6.x); fma2(A[12], h0.y, w6.y);
            fma2(A[13], h1.x, w6.x); fma2(A[13], h1.y, w6.y);
            fma2(A[14], h0.x, w7.x); fma2(A[14], h0.y, w7.y);
            fma2(A[15], h1.x, w7.x); fma2(A[15], h1.y, w7.y);
        }

        float s[16];
#pragma unroll
        for (int m = 0; m < 16; m++) { float2 f = unpk(A[m]); s[m] = f.x + f.y; }

        // 8-lane tree reduction; lane k ends with row 8g+k, both batches.
        float r8[8];
#pragma unroll
        for (int q = 0; q < 8; q++) {              // q = (j&3)*2 + b
            float keep = s4 ? s[q + 8] : s[q];
            float send = s4 ? s[q] : s[q + 8];
            r8[q] = keep + __shfl_xor_sync(0xffffffffu, send, 4);
        }
        float r4[4];
#pragma unroll
        for (int q = 0; q < 4; q++) {              // q = (j&1)*2 + b
            float keep = s2 ? r8[q + 4] : r8[q];
            float send = s2 ? r8[q] : r8[q + 4];
            r4[q] = keep + __shfl_xor_sync(0xffffffffu, send, 2);
        }
        float v0, v1;
        {
            float keep0 = s1 ? r4[2] : r4[0], send0 = s1 ? r4[0] : r4[2];
            float keep1 = s1 ? r4[3] : r4[1], send1 = s1 ? r4[1] : r4[3];
            v0 = keep0 + __shfl_xor_sync(0xffffffffu, send0, 1);
            v1 = keep1 + __shfl_xor_sync(0xffffffffu, send1, 1);
        }

        float pre0 = v0 + fmaf(sx[ts],      wih, bias);
        float pre1 = v1 + fmaf(sx[TT + ts], wih, bias);

        const int wo = (rb ^ 1) * (BC * HH);
        hbuf[wo + wpos0] = ftanh(pre0);
        hbuf[wo + wpos1] = ftanh(pre1);
        __syncthreads();
        rb ^= 1;
    }

    // ---- Epilogue: out[b,p] = h_T[b,:] . W_out[p,:] + b_out[p]  (h in buf 0)
    if (t < BC * PP) {
        const int bb = t / PP;
        const int p  = t % PP;
        const float* wo = W_out + (size_t)p * HH;
        float acc = b_out[p];
#pragma unroll 8
        for (int col = 0; col < HH; col++)
            acc = fmaf(hbuf[hword(col, bb)], wo[col], acc);
        out[(size_t)(b0 + bb) * PP + p] = acc;
    }
}

extern "C" void kernel_launch(void* const* d_in, const int* in_sizes, int n_in,
                              void* d_out, int out_size)
{
    const float* x     = (const float*)d_in[0];
    const float* W_ih  = (const float*)d_in[1];
    const float* W_hh  = (const float*)d_in[2];
    const float* b_ih  = (const float*)d_in[3];
    const float* b_hh  = (const float*)d_in[4];
    const float* W_out = (const float*)d_in[5];
    const float* b_out = (const float*)d_in[6];
    float* out = (float*)d_out;

    cudaFuncSetAttribute(rnn_persistent_kernel,
                         cudaFuncAttributeMaxDynamicSharedMemorySize, (int)SMEM_TOTAL);
    rnn_persistent_kernel<<<NCTA, NTHR, SMEM_TOTAL>>>(x, W_ih, W_hh, b_ih, b_hh,
                                                      W_out, b_out, out);
}